// round 5
// baseline (speedup 1.0000x reference)
#include <cuda_runtime.h>
#include <math.h>

#define B_  512
#define R_  1152
#define C_  8
#define J_  10
#define O_  16
#define JO_ 160

// Scratch (device globals: no allocations allowed in kernel_launch)
__device__ float g_U[(size_t)B_ * R_ * JO_];   // u_hat [B,R,J*O], fp32, 377 MB
__device__ float g_S[3][B_ * JO_];             // s accumulators per iteration
__device__ float g_V0[B_ * JO_];               // v0
__device__ float g_VSUM[B_ * JO_];             // v0 + v1

// ---------------------------------------------------------------------------
__global__ void k_zero() {
    int i = blockIdx.x * blockDim.x + threadIdx.x;
    if (i < 3 * B_ * JO_) ((float*)g_S)[i] = 0.0f;
}

// ---------------------------------------------------------------------------
// u_hat[b,r,jo] = sum_c W[r,jo,c] * x[b,r,c]; also accumulate sum_r u_hat
// into g_S[0] (iteration 0 has uniform c = 1/J; scaling applied in squash).
// Block: 256 threads = 8 warps = 8 b's sharing one r-chunk & the W smem tile.
// Grid: (B/8, 9) — 9 chunks of 128 r each.
__global__ void __launch_bounds__(256) k_uhat(const float* __restrict__ x,
                                              const float* __restrict__ W) {
    __shared__ float w_s[4][8][164];   // [rr][c][jo], padded 164 to avoid STS conflicts
    const int tid  = threadIdx.x;
    const int warp = tid >> 5, lane = tid & 31;
    const int b    = blockIdx.x * 8 + warp;
    const int r0   = blockIdx.y * 128;

    float sacc[5] = {0.f, 0.f, 0.f, 0.f, 0.f};

    for (int rb = 0; rb < 128; rb += 4) {
        const int rbase = r0 + rb;
        __syncthreads();
        // cooperative load of W[rbase..rbase+4), transposed to [c][jo]
        for (int i = tid; i < 4 * 1280; i += 256) {
            int rr  = i / 1280;
            int rem = i - rr * 1280;           // rem = jo*8 + c
            w_s[rr][rem & 7][rem >> 3] = W[(size_t)(rbase + rr) * 1280 + rem];
        }
        __syncthreads();

        // one coalesced load covers x[b, rbase..rbase+4, 0..8): lane = rr*8+c
        float xv = x[(size_t)b * (R_ * C_) + (size_t)rbase * C_ + lane];

        #pragma unroll
        for (int rr = 0; rr < 4; rr++) {
            float xc[8];
            #pragma unroll
            for (int c = 0; c < 8; c++)
                xc[c] = __shfl_sync(0xffffffffu, xv, rr * 8 + c);

            float* up = &g_U[((size_t)b * R_ + rbase + rr) * JO_];
            #pragma unroll
            for (int k = 0; k < 5; k++) {
                float u = 0.f;
                #pragma unroll
                for (int c = 0; c < 8; c++)
                    u = fmaf(w_s[rr][c][lane + 32 * k], xc[c], u);
                up[lane + 32 * k] = u;
                sacc[k] += u;
            }
        }
    }
    #pragma unroll
    for (int k = 0; k < 5; k++)
        atomicAdd(&g_S[0][b * JO_ + lane + 32 * k], sacc[k]);
}

// ---------------------------------------------------------------------------
// One routing iteration: logits a[b,r,j] = u_hat[b,r,j,:] . V[b,j,:]
// (V = v0 for iter1, v0+v1 for iter2; b_ij never materialized), softmax over
// j=10, accumulate s[b,j,o] = sum_r c * u_hat.
// One warp owns (b, slice of 128 r). Lane l holds jo = l + 32k, k=0..4:
// lanes 0-15 hold even j (= 2k), lanes 16-31 odd j (= 2k+1).
__global__ void __launch_bounds__(256) k_route(int vsel, int ssel) {
    const int lane = threadIdx.x & 31;
    const int unit = blockIdx.x * 8 + (threadIdx.x >> 5);
    const int b    = unit / 9;
    const int sl   = unit - b * 9;

    const float* __restrict__ V = vsel ? g_VSUM : g_V0;

    float v[5], sacc[5] = {0.f, 0.f, 0.f, 0.f, 0.f};
    #pragma unroll
    for (int k = 0; k < 5; k++)
        v[k] = V[b * JO_ + lane + 32 * k];

    const float* __restrict__ up =
        &g_U[((size_t)b * R_ + (size_t)sl * 128) * JO_ + lane];

    #pragma unroll 2
    for (int r = 0; r < 128; r++) {
        float u[5], ap[5];
        #pragma unroll
        for (int k = 0; k < 5; k++) u[k] = up[32 * k];
        up += JO_;

        #pragma unroll
        for (int k = 0; k < 5; k++) ap[k] = u[k] * v[k];

        // reduce over o (16 lanes per j-group)
        #pragma unroll
        for (int d = 1; d < 16; d <<= 1) {
            #pragma unroll
            for (int k = 0; k < 5; k++)
                ap[k] += __shfl_xor_sync(0xffffffffu, ap[k], d);
        }
        // ap[k] = a[j], j = 2k + (lane>>4). Softmax over all 10 j:
        float m = ap[0];
        #pragma unroll
        for (int k = 1; k < 5; k++) m = fmaxf(m, ap[k]);
        m = fmaxf(m, __shfl_xor_sync(0xffffffffu, m, 16));

        float e[5], z = 0.f;
        #pragma unroll
        for (int k = 0; k < 5; k++) { e[k] = __expf(ap[k] - m); z += e[k]; }
        z += __shfl_xor_sync(0xffffffffu, z, 16);
        float rz = __fdividef(1.0f, z);

        #pragma unroll
        for (int k = 0; k < 5; k++)
            sacc[k] = fmaf(e[k] * rz, u[k], sacc[k]);
    }

    float* __restrict__ Sout = g_S[ssel];
    #pragma unroll
    for (int k = 0; k < 5; k++)
        atomicAdd(&Sout[b * JO_ + lane + 32 * k], sacc[k]);
}

// ---------------------------------------------------------------------------
// v = squash(S * scale). mode 0: write g_V0. mode 1: g_VSUM = v + g_V0.
// mode 2: write dout (final output, [B,J,O,1] contiguous).
__global__ void k_squash(int ssel, float scale, int mode,
                         float* __restrict__ dout) {
    int i = blockIdx.x * blockDim.x + threadIdx.x;   // over B*J = 5120
    if (i >= B_ * J_) return;
    const float* s = g_S[ssel] + (size_t)i * O_;

    float sv[O_];
    float sq = 0.f;
    #pragma unroll
    for (int o = 0; o < O_; o++) {
        float t = s[o] * scale;
        sv[o] = t;
        sq += t * t;
    }
    float f = (sq / (1.0f + sq)) * rsqrtf(sq + 1e-8f);

    #pragma unroll
    for (int o = 0; o < O_; o++) {
        float vv = sv[o] * f;
        if (mode == 0)      g_V0[(size_t)i * O_ + o]   = vv;
        else if (mode == 1) g_VSUM[(size_t)i * O_ + o] = vv + g_V0[(size_t)i * O_ + o];
        else                dout[(size_t)i * O_ + o]   = vv;
    }
}

// ---------------------------------------------------------------------------
extern "C" void kernel_launch(void* const* d_in, const int* in_sizes, int n_in,
                              void* d_out, int out_size) {
    const float* x = (const float*)d_in[0];   // [512,1152,8]
    const float* W = (const float*)d_in[1];   // [1152,10,16,8]
    float* out = (float*)d_out;               // [512,10,16,1]
    (void)in_sizes; (void)n_in; (void)out_size;

    k_zero<<<240, 1024>>>();                          // zero S0,S1,S2
    k_uhat<<<dim3(64, 9), 256>>>(x, W);               // u_hat + sum_r -> S0
    k_squash<<<20, 256>>>(0, 1.0f / (float)J_, 0, nullptr);  // v0
    k_route<<<576, 256>>>(0, 1);                      // iter 1 -> S1 (logits u.v0)
    k_squash<<<20, 256>>>(1, 1.0f, 1, nullptr);       // v1, VSUM = v0+v1
    k_route<<<576, 256>>>(1, 2);                      // iter 2 -> S2 (logits u.(v0+v1))
    k_squash<<<20, 256>>>(2, 1.0f, 2, out);           // v2 -> output
}

// round 6
// speedup vs baseline: 1.5990x; 1.5990x over previous
#include <cuda_runtime.h>
#include <math.h>

#define B_  512
#define R_  1152
#define C_  8
#define J_  10
#define O_  16
#define JO_ 160

// Scratch (device globals: no allocations allowed in kernel_launch)
__device__ float g_U[(size_t)B_ * R_ * JO_];   // u_hat [B,R,J*O], fp32, 377 MB
__device__ float g_S[3][B_ * JO_];             // s accumulators per iteration
__device__ float g_V0[B_ * JO_];               // v0
__device__ float g_VSUM[B_ * JO_];             // v0 + v1

// ---------------------------------------------------------------------------
__global__ void k_zero() {
    int i = blockIdx.x * blockDim.x + threadIdx.x;
    if (i < 3 * B_ * JO_) ((float*)g_S)[i] = 0.0f;
}

// ---------------------------------------------------------------------------
// u_hat[b,r,jo] = sum_c W[r,jo,c] * x[b,r,c]; also accumulate sum_r u_hat
// into g_S[0] (iteration 0 has uniform c = 1/J; scaling applied in squash).
//
// v2: no smem. Each warp owns (8 batches, 16-r slice). W[r] (1280 floats) is
// loaded ONCE per r into 40 registers via 10 coalesced LDG.128 (lane l holds
// W[r, jo=l+32k, 0..8)), then reused for all 8 batches -> W-operand traffic
// per FMA drops 8x and the smem crossbar bottleneck disappears entirely.
// Units: 64 b-groups x 72 slices = 4608 warps.
__global__ void __launch_bounds__(256) k_uhat(const float* __restrict__ x,
                                              const float* __restrict__ W) {
    const int tid  = threadIdx.x;
    const int lane = tid & 31;
    const int unit = blockIdx.x * 8 + (tid >> 5);
    const int bg   = unit / 72;            // 64 groups of 8 b
    const int sl   = unit - bg * 72;       // 72 slices of 16 r
    const int b0   = bg * 8;
    const int r0   = sl * 16;

    float sacc[8][5];
    #pragma unroll
    for (int bb = 0; bb < 8; bb++)
        #pragma unroll
        for (int k = 0; k < 5; k++) sacc[bb][k] = 0.f;

    for (int rq = 0; rq < 4; rq++) {
        const int rbase = r0 + rq * 4;

        // x chunk: per b, 4 r x 8 c = 32 floats, one coalesced load each
        float xq[8];
        #pragma unroll
        for (int bb = 0; bb < 8; bb++)
            xq[bb] = x[(size_t)(b0 + bb) * (R_ * C_) + (size_t)rbase * C_ + lane];

        #pragma unroll
        for (int rr = 0; rr < 4; rr++) {
            const int r = rbase + rr;

            // W[r] -> registers: lane l holds W[r, l+32k, 0..8) as 2 float4
            float4 wa[5], wb[5];
            const float4* Wp =
                (const float4*)(W + (size_t)r * 1280 + (size_t)lane * 8);
            #pragma unroll
            for (int k = 0; k < 5; k++) {
                wa[k] = Wp[k * 64];
                wb[k] = Wp[k * 64 + 1];
            }

            float* up = &g_U[((size_t)b0 * R_ + r) * JO_ + lane];
            #pragma unroll
            for (int bb = 0; bb < 8; bb++) {
                float xc[8];
                #pragma unroll
                for (int c = 0; c < 8; c++)
                    xc[c] = __shfl_sync(0xffffffffu, xq[bb], rr * 8 + c);

                #pragma unroll
                for (int k = 0; k < 5; k++) {
                    float u = wa[k].x * xc[0];
                    u = fmaf(wa[k].y, xc[1], u);
                    u = fmaf(wa[k].z, xc[2], u);
                    u = fmaf(wa[k].w, xc[3], u);
                    u = fmaf(wb[k].x, xc[4], u);
                    u = fmaf(wb[k].y, xc[5], u);
                    u = fmaf(wb[k].z, xc[6], u);
                    u = fmaf(wb[k].w, xc[7], u);
                    up[(size_t)bb * (R_ * JO_) + 32 * k] = u;
                    sacc[bb][k] += u;
                }
            }
        }
    }

    #pragma unroll
    for (int bb = 0; bb < 8; bb++)
        #pragma unroll
        for (int k = 0; k < 5; k++)
            atomicAdd(&g_S[0][(b0 + bb) * JO_ + lane + 32 * k], sacc[bb][k]);
}

// ---------------------------------------------------------------------------
// One routing iteration: logits a[b,r,j] = u_hat[b,r,j,:] . V[b,j,:]
// (V = v0 for iter1, v0+v1 for iter2; b_ij never materialized), softmax over
// j=10, accumulate s[b,j,o] = sum_r c * u_hat.
// One warp owns (b, slice of 64 r). Lane l holds jo = l + 32k, k=0..4:
// lanes 0-15 hold even j (= 2k), lanes 16-31 odd j (= 2k+1).
// v2: 18 slices of 64 r -> 9216 warps (97% warp-slot fill, was 45%).
__global__ void __launch_bounds__(256) k_route(int vsel, int ssel) {
    const int lane = threadIdx.x & 31;
    const int unit = blockIdx.x * 8 + (threadIdx.x >> 5);
    const int b    = unit / 18;
    const int sl   = unit - b * 18;

    const float* __restrict__ V = vsel ? g_VSUM : g_V0;

    float v[5], sacc[5] = {0.f, 0.f, 0.f, 0.f, 0.f};
    #pragma unroll
    for (int k = 0; k < 5; k++)
        v[k] = V[b * JO_ + lane + 32 * k];

    const float* __restrict__ up =
        &g_U[((size_t)b * R_ + (size_t)sl * 64) * JO_ + lane];

    #pragma unroll 4
    for (int r = 0; r < 64; r++) {
        float u[5], ap[5];
        #pragma unroll
        for (int k = 0; k < 5; k++) u[k] = up[32 * k];
        up += JO_;

        #pragma unroll
        for (int k = 0; k < 5; k++) ap[k] = u[k] * v[k];

        // reduce over o (16 lanes per j-group)
        #pragma unroll
        for (int d = 1; d < 16; d <<= 1) {
            #pragma unroll
            for (int k = 0; k < 5; k++)
                ap[k] += __shfl_xor_sync(0xffffffffu, ap[k], d);
        }
        // ap[k] = a[j], j = 2k + (lane>>4). Softmax over all 10 j:
        float m = ap[0];
        #pragma unroll
        for (int k = 1; k < 5; k++) m = fmaxf(m, ap[k]);
        m = fmaxf(m, __shfl_xor_sync(0xffffffffu, m, 16));

        float e[5], z = 0.f;
        #pragma unroll
        for (int k = 0; k < 5; k++) { e[k] = __expf(ap[k] - m); z += e[k]; }
        z += __shfl_xor_sync(0xffffffffu, z, 16);
        float rz = __fdividef(1.0f, z);

        #pragma unroll
        for (int k = 0; k < 5; k++)
            sacc[k] = fmaf(e[k] * rz, u[k], sacc[k]);
    }

    float* __restrict__ Sout = g_S[ssel];
    #pragma unroll
    for (int k = 0; k < 5; k++)
        atomicAdd(&Sout[b * JO_ + lane + 32 * k], sacc[k]);
}

// ---------------------------------------------------------------------------
// v = squash(S * scale). mode 0: write g_V0. mode 1: g_VSUM = v + g_V0.
// mode 2: write dout (final output, [B,J,O,1] contiguous).
__global__ void k_squash(int ssel, float scale, int mode,
                         float* __restrict__ dout) {
    int i = blockIdx.x * blockDim.x + threadIdx.x;   // over B*J = 5120
    if (i >= B_ * J_) return;
    const float* s = g_S[ssel] + (size_t)i * O_;

    float sv[O_];
    float sq = 0.f;
    #pragma unroll
    for (int o = 0; o < O_; o++) {
        float t = s[o] * scale;
        sv[o] = t;
        sq += t * t;
    }
    float f = (sq / (1.0f + sq)) * rsqrtf(sq + 1e-8f);

    #pragma unroll
    for (int o = 0; o < O_; o++) {
        float vv = sv[o] * f;
        if (mode == 0)      g_V0[(size_t)i * O_ + o]   = vv;
        else if (mode == 1) g_VSUM[(size_t)i * O_ + o] = vv + g_V0[(size_t)i * O_ + o];
        else                dout[(size_t)i * O_ + o]   = vv;
    }
}

// ---------------------------------------------------------------------------
extern "C" void kernel_launch(void* const* d_in, const int* in_sizes, int n_in,
                              void* d_out, int out_size) {
    const float* x = (const float*)d_in[0];   // [512,1152,8]
    const float* W = (const float*)d_in[1];   // [1152,10,16,8]
    float* out = (float*)d_out;               // [512,10,16,1]
    (void)in_sizes; (void)n_in; (void)out_size;

    k_zero<<<240, 1024>>>();                          // zero S0,S1,S2
    k_uhat<<<576, 256>>>(x, W);                       // u_hat + sum_r -> S0
    k_squash<<<20, 256>>>(0, 1.0f / (float)J_, 0, nullptr);  // v0
    k_route<<<1152, 256>>>(0, 1);                     // iter 1 -> S1 (logits u.v0)
    k_squash<<<20, 256>>>(1, 1.0f, 1, nullptr);       // v1, VSUM = v0+v1
    k_route<<<1152, 256>>>(1, 2);                     // iter 2 -> S2 (logits u.(v0+v1))
    k_squash<<<20, 256>>>(2, 1.0f, 2, out);           // v2 -> output
}

// round 7
// speedup vs baseline: 2.0046x; 1.2537x over previous
#include <cuda_runtime.h>
#include <cuda_fp16.h>
#include <math.h>

#define B_  512
#define R_  1152
#define C_  8
#define J_  10
#define O_  16
#define JO_ 160

// Scratch (device globals: no allocations allowed in kernel_launch)
// u_hat stored fp16, packed across batch pairs: g_U16[p, r, jo] = (u[2p], u[2p+1])
__device__ __half2 g_U16[(size_t)(B_ / 2) * R_ * JO_];   // 188 MB
__device__ float   g_S[3][B_ * JO_];                     // s accumulators
__device__ float   g_V0[B_ * JO_];                       // v0
__device__ float   g_VSUM[B_ * JO_];                     // v0 + v1

// ---------------------------------------------------------------------------
__global__ void k_zero() {
    int i = blockIdx.x * blockDim.x + threadIdx.x;
    if (i < 3 * B_ * JO_) ((float*)g_S)[i] = 0.0f;
}

// ---------------------------------------------------------------------------
// u_hat[b,r,jo] = sum_c W[r,jo,c] * x[b,r,c]; fused sum_r u_hat -> g_S[0]
// (iteration 0 has uniform c; 1/J applied in squash).
// Each warp owns (8 batches = 4 pairs, 16-r slice). W[r] lives in 40 regs,
// reused across the 8 batches. Even-b results are held one iteration and
// stored packed with the odd-b results as half2 (halves store traffic).
__global__ void __launch_bounds__(256) k_uhat(const float* __restrict__ x,
                                              const float* __restrict__ W) {
    const int tid  = threadIdx.x;
    const int lane = tid & 31;
    const int unit = blockIdx.x * 8 + (tid >> 5);
    const int bg   = unit / 72;            // 64 groups of 8 b
    const int sl   = unit - bg * 72;       // 72 slices of 16 r
    const int b0   = bg * 8;
    const int r0   = sl * 16;

    float sacc[8][5];
    #pragma unroll
    for (int bb = 0; bb < 8; bb++)
        #pragma unroll
        for (int k = 0; k < 5; k++) sacc[bb][k] = 0.f;

    for (int rq = 0; rq < 4; rq++) {
        const int rbase = r0 + rq * 4;

        // x chunk: per b, 4 r x 8 c = 32 floats, one coalesced load each
        float xq[8];
        #pragma unroll
        for (int bb = 0; bb < 8; bb++)
            xq[bb] = x[(size_t)(b0 + bb) * (R_ * C_) + (size_t)rbase * C_ + lane];

        #pragma unroll
        for (int rr = 0; rr < 4; rr++) {
            const int r = rbase + rr;

            // W[r] -> registers: lane l holds W[r, l+32k, 0..8) as 2 float4
            float4 wa[5], wb[5];
            const float4* Wp =
                (const float4*)(W + (size_t)r * 1280 + (size_t)lane * 8);
            #pragma unroll
            for (int k = 0; k < 5; k++) {
                wa[k] = Wp[k * 64];
                wb[k] = Wp[k * 64 + 1];
            }

            float uhold[5];
            #pragma unroll
            for (int bb = 0; bb < 8; bb++) {
                float xc[8];
                #pragma unroll
                for (int c = 0; c < 8; c++)
                    xc[c] = __shfl_sync(0xffffffffu, xq[bb], rr * 8 + c);

                float u[5];
                #pragma unroll
                for (int k = 0; k < 5; k++) {
                    float t = wa[k].x * xc[0];
                    t = fmaf(wa[k].y, xc[1], t);
                    t = fmaf(wa[k].z, xc[2], t);
                    t = fmaf(wa[k].w, xc[3], t);
                    t = fmaf(wb[k].x, xc[4], t);
                    t = fmaf(wb[k].y, xc[5], t);
                    t = fmaf(wb[k].z, xc[6], t);
                    t = fmaf(wb[k].w, xc[7], t);
                    u[k] = t;
                    sacc[bb][k] += t;
                }

                if (bb & 1) {
                    // pack (even b, odd b) and store as half2
                    __half2* up = g_U16 +
                        ((size_t)((b0 >> 1) + (bb >> 1)) * R_ + r) * JO_ + lane;
                    #pragma unroll
                    for (int k = 0; k < 5; k++)
                        up[32 * k] = __floats2half2_rn(uhold[k], u[k]);
                } else {
                    #pragma unroll
                    for (int k = 0; k < 5; k++) uhold[k] = u[k];
                }
            }
        }
    }

    #pragma unroll
    for (int bb = 0; bb < 8; bb++)
        #pragma unroll
        for (int k = 0; k < 5; k++)
            atomicAdd(&g_S[0][(b0 + bb) * JO_ + lane + 32 * k], sacc[bb][k]);
}

// ---------------------------------------------------------------------------
// One routing iteration on a BATCH PAIR per warp: logits for b0 and b1 ride
// in the .x/.y halves of every half2 through the butterfly, so the 40-inst
// o-reduction is amortized over two batches. Softmax tail in fp32 using
// exp2 (log2(e) folded into v). Accumulation in fp32.
// Lane l holds jo = l + 32k, k=0..4: lanes 0-15 j=2k, lanes 16-31 j=2k+1.
// Units: 256 pairs x 24 slices of 48 r = 6144 warps.
__global__ void __launch_bounds__(256, 6) k_route(int vsel, int ssel) {
    const int lane = threadIdx.x & 31;
    const int unit = blockIdx.x * 8 + (threadIdx.x >> 5);
    const int p    = unit / 24;
    const int sl   = unit - p * 24;
    const int b0   = 2 * p, b1 = b0 + 1;

    const float* __restrict__ V = vsel ? g_VSUM : g_V0;
    const float LOG2E = 1.4426950408889634f;

    __half2 v2[5];
    float sacc0[5] = {0.f, 0.f, 0.f, 0.f, 0.f};
    float sacc1[5] = {0.f, 0.f, 0.f, 0.f, 0.f};
    #pragma unroll
    for (int k = 0; k < 5; k++) {
        int jo = lane + 32 * k;
        v2[k] = __floats2half2_rn(V[b0 * JO_ + jo] * LOG2E,
                                  V[b1 * JO_ + jo] * LOG2E);
    }

    const __half2* __restrict__ up =
        g_U16 + ((size_t)p * R_ + (size_t)sl * 48) * JO_ + lane;

    #pragma unroll 4
    for (int r = 0; r < 48; r++) {
        __half2 u2[5], ap2[5];
        #pragma unroll
        for (int k = 0; k < 5; k++) u2[k] = up[32 * k];
        up += JO_;

        #pragma unroll
        for (int k = 0; k < 5; k++) ap2[k] = __hmul2(u2[k], v2[k]);

        // reduce over o (16 lanes per j-group), both batches per op
        #pragma unroll
        for (int d = 1; d < 16; d <<= 1) {
            #pragma unroll
            for (int k = 0; k < 5; k++)
                ap2[k] = __hadd2(ap2[k],
                                 __shfl_xor_sync(0xffffffffu, ap2[k], d));
        }

        // ap2[k] = (a[b0,j]*log2e, a[b1,j]*log2e), j = 2k + (lane>>4)
        float a0[5], a1[5];
        #pragma unroll
        for (int k = 0; k < 5; k++) {
            float2 t = __half22float2(ap2[k]);
            a0[k] = t.x; a1[k] = t.y;
        }

        float m0 = a0[0], m1 = a1[0];
        #pragma unroll
        for (int k = 1; k < 5; k++) {
            m0 = fmaxf(m0, a0[k]);
            m1 = fmaxf(m1, a1[k]);
        }
        m0 = fmaxf(m0, __shfl_xor_sync(0xffffffffu, m0, 16));
        m1 = fmaxf(m1, __shfl_xor_sync(0xffffffffu, m1, 16));

        float z0 = 0.f, z1 = 0.f;
        #pragma unroll
        for (int k = 0; k < 5; k++) {
            a0[k] = exp2f(a0[k] - m0); z0 += a0[k];
            a1[k] = exp2f(a1[k] - m1); z1 += a1[k];
        }
        z0 += __shfl_xor_sync(0xffffffffu, z0, 16);
        z1 += __shfl_xor_sync(0xffffffffu, z1, 16);
        float rz0 = __fdividef(1.0f, z0);
        float rz1 = __fdividef(1.0f, z1);

        #pragma unroll
        for (int k = 0; k < 5; k++) {
            float2 uf = __half22float2(u2[k]);
            sacc0[k] = fmaf(a0[k] * rz0, uf.x, sacc0[k]);
            sacc1[k] = fmaf(a1[k] * rz1, uf.y, sacc1[k]);
        }
    }

    float* __restrict__ Sout = g_S[ssel];
    #pragma unroll
    for (int k = 0; k < 5; k++) {
        atomicAdd(&Sout[b0 * JO_ + lane + 32 * k], sacc0[k]);
        atomicAdd(&Sout[b1 * JO_ + lane + 32 * k], sacc1[k]);
    }
}

// ---------------------------------------------------------------------------
// v = squash(S * scale). mode 0: write g_V0. mode 1: g_VSUM = v + g_V0.
// mode 2: write dout (final output, [B,J,O,1] contiguous).
__global__ void k_squash(int ssel, float scale, int mode,
                         float* __restrict__ dout) {
    int i = blockIdx.x * blockDim.x + threadIdx.x;   // over B*J = 5120
    if (i >= B_ * J_) return;
    const float* s = g_S[ssel] + (size_t)i * O_;

    float sv[O_];
    float sq = 0.f;
    #pragma unroll
    for (int o = 0; o < O_; o++) {
        float t = s[o] * scale;
        sv[o] = t;
        sq += t * t;
    }
    float f = (sq / (1.0f + sq)) * rsqrtf(sq + 1e-8f);

    #pragma unroll
    for (int o = 0; o < O_; o++) {
        float vv = sv[o] * f;
        if (mode == 0)      g_V0[(size_t)i * O_ + o]   = vv;
        else if (mode == 1) g_VSUM[(size_t)i * O_ + o] = vv + g_V0[(size_t)i * O_ + o];
        else                dout[(size_t)i * O_ + o]   = vv;
    }
}

// ---------------------------------------------------------------------------
extern "C" void kernel_launch(void* const* d_in, const int* in_sizes, int n_in,
                              void* d_out, int out_size) {
    const float* x = (const float*)d_in[0];   // [512,1152,8]
    const float* W = (const float*)d_in[1];   // [1152,10,16,8]
    float* out = (float*)d_out;               // [512,10,16,1]
    (void)in_sizes; (void)n_in; (void)out_size;

    k_zero<<<240, 1024>>>();                          // zero S0,S1,S2
    k_uhat<<<576, 256>>>(x, W);                       // u_hat(fp16) + sum_r -> S0
    k_squash<<<20, 256>>>(0, 1.0f / (float)J_, 0, nullptr);  // v0
    k_route<<<768, 256>>>(0, 1);                      // iter 1 -> S1 (logits u.v0)
    k_squash<<<20, 256>>>(1, 1.0f, 1, nullptr);       // v1, VSUM = v0+v1
    k_route<<<768, 256>>>(1, 2);                      // iter 2 -> S2 (logits u.(v0+v1))
    k_squash<<<20, 256>>>(2, 1.0f, 2, out);           // v2 -> output
}

// round 8
// speedup vs baseline: 2.0397x; 1.0175x over previous
#include <cuda_runtime.h>
#include <cuda_fp16.h>
#include <math.h>

#define B_  512
#define R_  1152
#define C_  8
#define J_  10
#define O_  16
#define JO_ 160

// Scratch (device globals: no allocations allowed in kernel_launch)
// u_hat stored fp16, packed across batch pairs: g_U16[p, r, jo] = (u[2p], u[2p+1])
__device__ __half2 g_U16[(size_t)(B_ / 2) * R_ * JO_];   // 188 MB
__device__ float   g_S[3][B_ * JO_];                     // s accumulators
__device__ float   g_V0[B_ * JO_];                       // v0
__device__ float   g_VSUM[B_ * JO_];                     // v0 + v1

// ---------------------------------------------------------------------------
__global__ void k_zero() {
    int i = blockIdx.x * blockDim.x + threadIdx.x;
    if (i < 3 * B_ * JO_) ((float*)g_S)[i] = 0.0f;
}

// ---------------------------------------------------------------------------
// u_hat[b,r,jo] = sum_c W[r,jo,c] * x[b,r,c]; fused sum_r u_hat -> g_S[0]
// (iteration 0 has uniform c; 1/J applied in squash).
// Each warp owns (8 batches = 4 pairs, 8-r slice). W[r] lives in 40 regs,
// reused across the 8 batches; compute fp32, store packed half2.
// v3: 144 slices of 8 r -> 9216 warps (97% slot fill, was 48%) to hide the
// ~240cyc L2 latency of the W loads.
__global__ void __launch_bounds__(256) k_uhat(const float* __restrict__ x,
                                              const float* __restrict__ W) {
    const int tid  = threadIdx.x;
    const int lane = tid & 31;
    const int unit = blockIdx.x * 8 + (tid >> 5);
    const int bg   = unit / 144;           // 64 groups of 8 b
    const int sl   = unit - bg * 144;      // 144 slices of 8 r
    const int b0   = bg * 8;
    const int r0   = sl * 8;

    float sacc[8][5];
    #pragma unroll
    for (int bb = 0; bb < 8; bb++)
        #pragma unroll
        for (int k = 0; k < 5; k++) sacc[bb][k] = 0.f;

    #pragma unroll
    for (int rq = 0; rq < 2; rq++) {
        const int rbase = r0 + rq * 4;

        // x chunk: per b, 4 r x 8 c = 32 floats, one coalesced load each
        float xq[8];
        #pragma unroll
        for (int bb = 0; bb < 8; bb++)
            xq[bb] = x[(size_t)(b0 + bb) * (R_ * C_) + (size_t)rbase * C_ + lane];

        #pragma unroll
        for (int rr = 0; rr < 4; rr++) {
            const int r = rbase + rr;

            // W[r] -> registers: lane l holds W[r, l+32k, 0..8) as 2 float4
            float4 wa[5], wb[5];
            const float4* Wp =
                (const float4*)(W + (size_t)r * 1280 + (size_t)lane * 8);
            #pragma unroll
            for (int k = 0; k < 5; k++) {
                wa[k] = Wp[k * 64];
                wb[k] = Wp[k * 64 + 1];
            }

            float uhold[5];
            #pragma unroll
            for (int bb = 0; bb < 8; bb++) {
                float xc[8];
                #pragma unroll
                for (int c = 0; c < 8; c++)
                    xc[c] = __shfl_sync(0xffffffffu, xq[bb], rr * 8 + c);

                float u[5];
                #pragma unroll
                for (int k = 0; k < 5; k++) {
                    float t = wa[k].x * xc[0];
                    t = fmaf(wa[k].y, xc[1], t);
                    t = fmaf(wa[k].z, xc[2], t);
                    t = fmaf(wa[k].w, xc[3], t);
                    t = fmaf(wb[k].x, xc[4], t);
                    t = fmaf(wb[k].y, xc[5], t);
                    t = fmaf(wb[k].z, xc[6], t);
                    t = fmaf(wb[k].w, xc[7], t);
                    u[k] = t;
                    sacc[bb][k] += t;
                }

                if (bb & 1) {
                    // pack (even b, odd b) and store as half2
                    __half2* up = g_U16 +
                        ((size_t)((b0 >> 1) + (bb >> 1)) * R_ + r) * JO_ + lane;
                    #pragma unroll
                    for (int k = 0; k < 5; k++)
                        up[32 * k] = __floats2half2_rn(uhold[k], u[k]);
                } else {
                    #pragma unroll
                    for (int k = 0; k < 5; k++) uhold[k] = u[k];
                }
            }
        }
    }

    #pragma unroll
    for (int bb = 0; bb < 8; bb++)
        #pragma unroll
        for (int k = 0; k < 5; k++)
            atomicAdd(&g_S[0][(b0 + bb) * JO_ + lane + 32 * k], sacc[bb][k]);
}

// ---------------------------------------------------------------------------
// One routing iteration on a BATCH PAIR per warp: logits for b0 and b1 ride
// in the .x/.y halves of every half2 through the butterfly. Softmax tail in
// fp32, exp2 (log2(e) folded into v), NO max-subtraction: logits are bounded
// by ||u||*||v|| < ~30, exp2f of that is well inside fp32 range and the
// result is mathematically identical. Accumulation fp32.
// Lane l holds jo = l + 32k, k=0..4: lanes 0-15 j=2k, lanes 16-31 j=2k+1.
// v3: 256 pairs x 32 slices of 36 r = 8192 warps (86% slot fill).
__global__ void __launch_bounds__(256, 6) k_route(int vsel, int ssel) {
    const int lane = threadIdx.x & 31;
    const int unit = blockIdx.x * 8 + (threadIdx.x >> 5);
    const int p    = unit / 32;
    const int sl   = unit - p * 32;
    const int b0   = 2 * p, b1 = b0 + 1;

    const float* __restrict__ V = vsel ? g_VSUM : g_V0;
    const float LOG2E = 1.4426950408889634f;

    __half2 v2[5];
    float sacc0[5] = {0.f, 0.f, 0.f, 0.f, 0.f};
    float sacc1[5] = {0.f, 0.f, 0.f, 0.f, 0.f};
    #pragma unroll
    for (int k = 0; k < 5; k++) {
        int jo = lane + 32 * k;
        v2[k] = __floats2half2_rn(V[b0 * JO_ + jo] * LOG2E,
                                  V[b1 * JO_ + jo] * LOG2E);
    }

    const __half2* __restrict__ up =
        g_U16 + ((size_t)p * R_ + (size_t)sl * 36) * JO_ + lane;

    #pragma unroll 4
    for (int r = 0; r < 36; r++) {
        __half2 u2[5], ap2[5];
        #pragma unroll
        for (int k = 0; k < 5; k++) u2[k] = up[32 * k];
        up += JO_;

        #pragma unroll
        for (int k = 0; k < 5; k++) ap2[k] = __hmul2(u2[k], v2[k]);

        // reduce over o (16 lanes per j-group), both batches per op
        #pragma unroll
        for (int d = 1; d < 16; d <<= 1) {
            #pragma unroll
            for (int k = 0; k < 5; k++)
                ap2[k] = __hadd2(ap2[k],
                                 __shfl_xor_sync(0xffffffffu, ap2[k], d));
        }

        // ap2[k] = (a[b0,j], a[b1,j]) * log2e, j = 2k + (lane>>4)
        // exp WITHOUT max-subtraction (bounded logits, fp32-safe)
        float e0[5], e1[5];
        float z0 = 0.f, z1 = 0.f;
        #pragma unroll
        for (int k = 0; k < 5; k++) {
            e0[k] = exp2f(__low2float(ap2[k]));  z0 += e0[k];
            e1[k] = exp2f(__high2float(ap2[k])); z1 += e1[k];
        }
        z0 += __shfl_xor_sync(0xffffffffu, z0, 16);
        z1 += __shfl_xor_sync(0xffffffffu, z1, 16);
        float rz0 = __fdividef(1.0f, z0);
        float rz1 = __fdividef(1.0f, z1);

        #pragma unroll
        for (int k = 0; k < 5; k++) {
            float2 uf = __half22float2(u2[k]);
            sacc0[k] = fmaf(e0[k] * rz0, uf.x, sacc0[k]);
            sacc1[k] = fmaf(e1[k] * rz1, uf.y, sacc1[k]);
        }
    }

    float* __restrict__ Sout = g_S[ssel];
    #pragma unroll
    for (int k = 0; k < 5; k++) {
        atomicAdd(&Sout[b0 * JO_ + lane + 32 * k], sacc0[k]);
        atomicAdd(&Sout[b1 * JO_ + lane + 32 * k], sacc1[k]);
    }
}

// ---------------------------------------------------------------------------
// v = squash(S * scale). mode 0: write g_V0. mode 1: g_VSUM = v + g_V0.
// mode 2: write dout (final output, [B,J,O,1] contiguous).
__global__ void k_squash(int ssel, float scale, int mode,
                         float* __restrict__ dout) {
    int i = blockIdx.x * blockDim.x + threadIdx.x;   // over B*J = 5120
    if (i >= B_ * J_) return;
    const float* s = g_S[ssel] + (size_t)i * O_;

    float sv[O_];
    float sq = 0.f;
    #pragma unroll
    for (int o = 0; o < O_; o++) {
        float t = s[o] * scale;
        sv[o] = t;
        sq += t * t;
    }
    float f = (sq / (1.0f + sq)) * rsqrtf(sq + 1e-8f);

    #pragma unroll
    for (int o = 0; o < O_; o++) {
        float vv = sv[o] * f;
        if (mode == 0)      g_V0[(size_t)i * O_ + o]   = vv;
        else if (mode == 1) g_VSUM[(size_t)i * O_ + o] = vv + g_V0[(size_t)i * O_ + o];
        else                dout[(size_t)i * O_ + o]   = vv;
    }
}

// ---------------------------------------------------------------------------
extern "C" void kernel_launch(void* const* d_in, const int* in_sizes, int n_in,
                              void* d_out, int out_size) {
    const float* x = (const float*)d_in[0];   // [512,1152,8]
    const float* W = (const float*)d_in[1];   // [1152,10,16,8]
    float* out = (float*)d_out;               // [512,10,16,1]
    (void)in_sizes; (void)n_in; (void)out_size;

    k_zero<<<240, 1024>>>();                          // zero S0,S1,S2
    k_uhat<<<1152, 256>>>(x, W);                      // u_hat(fp16) + sum_r -> S0
    k_squash<<<20, 256>>>(0, 1.0f / (float)J_, 0, nullptr);  // v0
    k_route<<<1024, 256>>>(0, 1);                     // iter 1 -> S1 (logits u.v0)
    k_squash<<<20, 256>>>(1, 1.0f, 1, nullptr);       // v1, VSUM = v0+v1
    k_route<<<1024, 256>>>(1, 2);                     // iter 2 -> S2 (logits u.(v0+v1))
    k_squash<<<20, 256>>>(2, 1.0f, 2, out);           // v2 -> output
}